// round 1
// baseline (speedup 1.0000x reference)
#include <cuda_runtime.h>
#include <cstdint>

// Problem constants
#define B_    32
#define CIN   256
#define COUT  256
#define H_    56
#define W_    56
#define HW_   (H_*W_)          // 3136
#define KW    8                // 256 channels / 32 bits
#define KS    (COUT*CIN*9)     // stride between weight replicas k

// Scratch (device globals — no allocation allowed)
__device__ __align__(16) unsigned g_xbits[B_*H_*W_*KW];   // [b][h][w][cw]  bit=1 <=> x<0
__device__ __align__(16) unsigned g_wbits[COUT*9*KW];     // [co][tap][cw]  bit=1 <=> real_w<0
__device__ float g_factor[COUT];                          // scale[co]*alpha[co]

// ---------------------------------------------------------------------------
// Kernel A: mix the K weight replicas, pack sign bits, compute scale*alpha.
// grid = 256 (co), block = 256 (ci)
// ---------------------------------------------------------------------------
__global__ void prep_w_kernel(const float* __restrict__ W,
                              const float* __restrict__ RV,
                              const float* __restrict__ alpha) {
    const int co = blockIdx.x;
    const int ci = threadIdx.x;
    const float rv0 = RV[0], rv1 = RV[1], rv2 = RV[2], rv3 = RV[3];

    const float* p = W + ((long)co * CIN + ci) * 9;
    float real[9];
    float asum = 0.f;
#pragma unroll
    for (int t = 0; t < 9; t++) {
        float v = rv0 * p[t] + rv1 * p[t + KS] + rv2 * p[t + 2*KS] + rv3 * p[t + 3*KS];
        real[t] = v;
        asum += fabsf(v);
    }
#pragma unroll
    for (int t = 0; t < 9; t++) {
        unsigned bal = __ballot_sync(0xffffffffu, real[t] < 0.f);
        if ((ci & 31) == 0)
            g_wbits[co*72 + t*8 + (ci >> 5)] = bal;
    }
    // block reduce |real| sum
    __shared__ float red[256];
    red[ci] = asum;
    __syncthreads();
#pragma unroll
    for (int s = 128; s > 0; s >>= 1) {
        if (ci < s) red[ci] += red[ci + s];
        __syncthreads();
    }
    if (ci == 0)
        g_factor[co] = (red[0] * (1.f / 2304.f)) * alpha[co];
}

// ---------------------------------------------------------------------------
// Kernel B: pack sign(x) bits along channels. Coalesced read, smem transpose,
// warp ballot packs 32 channels into one word.
// grid = (8 cblocks, 56 h, 32 b), block = 256
// ---------------------------------------------------------------------------
__global__ void pack_x_kernel(const float* __restrict__ x) {
    const int cb = blockIdx.x;   // channel block (32 channels)
    const int h  = blockIdx.y;
    const int b  = blockIdx.z;
    const int tid = threadIdx.x;

    __shared__ float sx[32][57];   // [ci_local][w], padded: conflict-free columns

    // coalesced load: 32 channel-rows of 56 floats
    for (int i = tid; i < 32 * W_; i += 256) {
        int cl = i / W_;
        int w  = i % W_;
        sx[cl][w] = x[((long)(b * CIN + cb * 32 + cl)) * HW_ + h * W_ + w];
    }
    __syncthreads();

    const int lane = tid & 31;   // = channel within block
    const int warp = tid >> 5;   // 8 warps
    for (int w = warp; w < W_; w += 8) {
        float v = sx[lane][w];
        unsigned bal = __ballot_sync(0xffffffffu, v < 0.f);
        if (lane == 0)
            g_xbits[((b * H_ + h) * W_ + w) * KW + cb] = bal;
    }
}

// ---------------------------------------------------------------------------
// Kernel C: XNOR-popcount conv 3x3 pad 1.
// Tile: 14x14 spatial x 16 c_out per block. block = 224 threads
// (co_sub = tid/14 in [0,16), r = tid%14). Each thread: one (co,row),
// 14 outputs across w, sliding 3-column packed-x window.
// grid = (4 wtiles, 4 htiles, B*16 z) ; z = b*16 + co_block
// ---------------------------------------------------------------------------
__device__ __forceinline__ int pop4(uint4 a, uint4 b) {
    return __popc(a.x ^ b.x) + __popc(a.y ^ b.y) + __popc(a.z ^ b.z) + __popc(a.w ^ b.w);
}

__global__ __launch_bounds__(224, 2)
void conv_kernel(float* __restrict__ out) {
    const int w0 = blockIdx.x * 14;
    const int h0 = blockIdx.y * 14;
    const int b  = blockIdx.z >> 4;
    const int co_base = (blockIdx.z & 15) * 16;
    const int tid = threadIdx.x;
    const int co_sub = tid / 14;
    const int r      = tid % 14;

    __shared__ uint4 xs[16][16][2];   // [row][col][2]  (8 KB) : halo'd packed x tile
    __shared__ uint4 ws[16][9][2];    // [co_sub][tap][2] (4.5 KB)

    // load x tile (rows h0-1..h0+14, cols w0-1..w0+14), zero-pad outside
    for (int p = tid; p < 256; p += 224) {
        int i = p >> 4, j = p & 15;
        int gh = h0 - 1 + i, gw = w0 - 1 + j;
        uint4 a = make_uint4(0,0,0,0), c = make_uint4(0,0,0,0);
        if ((unsigned)gh < (unsigned)H_ && (unsigned)gw < (unsigned)W_) {
            const uint4* src = (const uint4*)&g_xbits[((b * H_ + gh) * W_ + gw) * KW];
            a = src[0]; c = src[1];
        }
        xs[i][j][0] = a; xs[i][j][1] = c;
    }
    // load weights for the 16 c_outs
    for (int p = tid; p < 16 * 9 * 2; p += 224) {
        int c = p / 18, rest = p % 18;
        int t = rest >> 1, half = rest & 1;
        ws[c][t][half] = *(const uint4*)&g_wbits[(co_base + c) * 72 + t * 8 + half * 4];
    }
    __syncthreads();

    int acc[14];
#pragma unroll
    for (int w = 0; w < 14; w++) acc[w] = 0;

    for (int dy = 0; dy < 3; dy++) {
        const int si = r + dy;                 // smem row
        const bool rowok = (unsigned)(h0 - 1 + si) < (unsigned)H_;

        uint4 wa[3], wb[3];
#pragma unroll
        for (int dx = 0; dx < 3; dx++) {
            wa[dx] = ws[co_sub][dy * 3 + dx][0];
            wb[dx] = ws[co_sub][dy * 3 + dx][1];
        }
        // sliding 3-column window of packed x
        uint4 qa0 = xs[si][0][0], qb0 = xs[si][0][1];
        uint4 qa1 = xs[si][1][0], qb1 = xs[si][1][1];
#pragma unroll
        for (int w = 0; w < 14; w++) {
            uint4 qa2 = xs[si][w + 2][0], qb2 = xs[si][w + 2][1];

            {   // dx = 0 : smem col w, global w0-1+w
                bool ok = rowok && ((unsigned)(w0 - 1 + w) < (unsigned)W_);
                int pc = pop4(qa0, wa[0]) + pop4(qb0, wb[0]);
                if (ok) acc[w] += 256 - 2 * pc;
            }
            {   // dx = 1 : always in range horizontally (w0+w in [0,56))
                if (rowok) {
                    int pc = pop4(qa1, wa[1]) + pop4(qb1, wb[1]);
                    acc[w] += 256 - 2 * pc;
                }
            }
            {   // dx = 2 : global w0+1+w
                bool ok = rowok && ((unsigned)(w0 + 1 + w) < (unsigned)W_);
                int pc = pop4(qa2, wa[2]) + pop4(qb2, wb[2]);
                if (ok) acc[w] += 256 - 2 * pc;
            }
            qa0 = qa1; qb0 = qb1;
            qa1 = qa2; qb1 = qb2;
        }
    }

    const int co = co_base + co_sub;
    const float fac = g_factor[co];
    float* dst = out + ((long)(b * COUT + co)) * HW_ + (h0 + r) * W_ + w0;
#pragma unroll
    for (int w = 0; w < 14; w++)
        dst[w] = fac * (float)acc[w];
}

// ---------------------------------------------------------------------------
extern "C" void kernel_launch(void* const* d_in, const int* in_sizes, int n_in,
                              void* d_out, int out_size) {
    const float* x     = (const float*)d_in[0];
    const float* W     = (const float*)d_in[1];
    const float* RV    = (const float*)d_in[2];
    const float* alpha = (const float*)d_in[3];
    float* out = (float*)d_out;

    prep_w_kernel<<<COUT, 256>>>(W, RV, alpha);
    pack_x_kernel<<<dim3(KW, H_, B_), 256>>>(x);
    conv_kernel<<<dim3(4, 4, B_ * 16), 224>>>(out);
}

// round 2
// speedup vs baseline: 1.5770x; 1.5770x over previous
#include <cuda_runtime.h>
#include <cstdint>

// Problem constants
#define B_    32
#define CIN   256
#define COUT  256
#define H_    56
#define W_    56
#define HW_   (H_*W_)          // 3136
#define KW    8                // 256 channels / 32 bits
#define KS    (COUT*CIN*9)     // stride between weight replicas k

// Scratch (device globals — no allocation allowed)
__device__ __align__(16) unsigned g_xbits[B_*H_*W_*KW];   // [b][h][w][cw]  bit=1 <=> x<0
__device__ __align__(16) unsigned g_wbits[COUT*9*KW];     // [co][tap][cw]  bit=1 <=> real_w<0
__device__ int   g_wS[COUT*9];                            // S[co][tap] = sum_ci sign(w)
__device__ float g_factor[COUT];                          // scale[co]*alpha[co]

// ---------------------------------------------------------------------------
// Kernel A: mix the K weight replicas, pack sign bits, compute scale*alpha
// and the per-tap sign sums S (padding correction terms).
// grid = 256 (co), block = 256 (ci)
// ---------------------------------------------------------------------------
__global__ void prep_w_kernel(const float* __restrict__ W,
                              const float* __restrict__ RV,
                              const float* __restrict__ alpha) {
    const int co = blockIdx.x;
    const int ci = threadIdx.x;
    const int warp = ci >> 5;
    const float rv0 = RV[0], rv1 = RV[1], rv2 = RV[2], rv3 = RV[3];

    const float* p = W + ((long)co * CIN + ci) * 9;
    float real[9];
    float asum = 0.f;
#pragma unroll
    for (int t = 0; t < 9; t++) {
        float v = rv0 * p[t] + rv1 * p[t + KS] + rv2 * p[t + 2*KS] + rv3 * p[t + 3*KS];
        real[t] = v;
        asum += fabsf(v);
    }

    __shared__ int popred[9][8];
#pragma unroll
    for (int t = 0; t < 9; t++) {
        unsigned bal = __ballot_sync(0xffffffffu, real[t] < 0.f);
        if ((ci & 31) == 0) {
            g_wbits[co*72 + t*8 + warp] = bal;
            popred[t][warp] = __popc(bal);
        }
    }
    // block reduce |real| sum
    __shared__ float red[256];
    red[ci] = asum;
    __syncthreads();
#pragma unroll
    for (int s = 128; s > 0; s >>= 1) {
        if (ci < s) red[ci] += red[ci + s];
        __syncthreads();
    }
    if (ci == 0)
        g_factor[co] = (red[0] * (1.f / 2304.f)) * alpha[co];
    if (ci < 9) {
        int s = 0;
#pragma unroll
        for (int wp = 0; wp < 8; wp++) s += popred[ci][wp];
        g_wS[co*9 + ci] = 256 - 2 * s;   // sum of signs for this tap
    }
}

// ---------------------------------------------------------------------------
// Kernel B: pack sign(x) bits along channels. Coalesced read, smem transpose,
// warp ballot packs 32 channels into one word.
// grid = (8 cblocks, 56 h, 32 b), block = 256
// ---------------------------------------------------------------------------
__global__ void pack_x_kernel(const float* __restrict__ x) {
    const int cb = blockIdx.x;   // channel block (32 channels)
    const int h  = blockIdx.y;
    const int b  = blockIdx.z;
    const int tid = threadIdx.x;

    __shared__ float sx[32][57];   // [ci_local][w], padded

    for (int i = tid; i < 32 * W_; i += 256) {
        int cl = i / W_;
        int w  = i % W_;
        sx[cl][w] = x[((long)(b * CIN + cb * 32 + cl)) * HW_ + h * W_ + w];
    }
    __syncthreads();

    const int lane = tid & 31;   // channel within block
    const int warp = tid >> 5;   // 8 warps
    for (int w = warp; w < W_; w += 8) {
        float v = sx[lane][w];
        unsigned bal = __ballot_sync(0xffffffffu, v < 0.f);
        if (lane == 0)
            g_xbits[((b * H_ + h) * W_ + w) * KW + cb] = bal;
    }
}

// ---------------------------------------------------------------------------
// Kernel C: XNOR-popcount conv 3x3 pad 1, no inner-loop predication.
// Tile: 14x14 spatial x 16 c_out per block, block = 224 threads.
// x tile stored TRANSPOSED [col][half][row] so inner-loop LDS (lanes vary in
// row) is bank-conflict-free. Padding handled by epilogue correction S.
// grid = (4 wtiles, 4 htiles, B*16 z) ; z = b*16 + co_block
// ---------------------------------------------------------------------------
__device__ __forceinline__ int pop4(uint4 a, uint4 b) {
    return __popc(a.x ^ b.x) + __popc(a.y ^ b.y) + __popc(a.z ^ b.z) + __popc(a.w ^ b.w);
}

__global__ __launch_bounds__(224, 2)
void conv_kernel(float* __restrict__ out) {
    const int w0 = blockIdx.x * 14;
    const int h0 = blockIdx.y * 14;
    const int b  = blockIdx.z >> 4;
    const int co_base = (blockIdx.z & 15) * 16;
    const int tid = threadIdx.x;
    const int co_sub = tid / 14;
    const int r      = tid % 14;

    __shared__ uint4 xs[16][2][16];   // [col][half][row]  (8 KB)
    __shared__ uint4 ws[16][9][2];    // [co_sub][tap][half] (4.5 KB)
    __shared__ int   sS[16][9];       // per-co tap sign sums

    // load x tile (rows h0-1..h0+14, cols w0-1..w0+14), zero outside image
    for (int p = tid; p < 256; p += 224) {
        int i = p >> 4, j = p & 15;          // i=row, j=col
        int gh = h0 - 1 + i, gw = w0 - 1 + j;
        uint4 a = make_uint4(0,0,0,0), c = make_uint4(0,0,0,0);
        if ((unsigned)gh < (unsigned)H_ && (unsigned)gw < (unsigned)W_) {
            const uint4* src = (const uint4*)&g_xbits[((b * H_ + gh) * W_ + gw) * KW];
            a = src[0]; c = src[1];
        }
        xs[j][0][i] = a; xs[j][1][i] = c;
    }
    // load weights + sign sums for the 16 c_outs
    for (int p = tid; p < 16 * 9 * 2; p += 224) {
        int c = p / 18, rest = p % 18;
        int t = rest >> 1, half = rest & 1;
        ws[c][t][half] = *(const uint4*)&g_wbits[(co_base + c) * 72 + t * 8 + half * 4];
        if (half == 0) sS[c][t] = g_wS[(co_base + c) * 9 + t];
    }
    __syncthreads();

    int acc[14];
#pragma unroll
    for (int w = 0; w < 14; w++) acc[w] = 0;

    for (int dy = 0; dy < 3; dy++) {
        const int si = r + dy;                 // smem row index

        uint4 wa[3], wb[3];
#pragma unroll
        for (int dx = 0; dx < 3; dx++) {
            wa[dx] = ws[co_sub][dy * 3 + dx][0];
            wb[dx] = ws[co_sub][dy * 3 + dx][1];
        }
        uint4 qa0 = xs[0][0][si], qb0 = xs[0][1][si];
        uint4 qa1 = xs[1][0][si], qb1 = xs[1][1][si];
#pragma unroll
        for (int w = 0; w < 14; w++) {
            uint4 qa2 = xs[w + 2][0][si], qb2 = xs[w + 2][1][si];
            int pc;
            pc  = pop4(qa0, wa[0]) + pop4(qb0, wb[0]);
            pc += pop4(qa1, wa[1]) + pop4(qb1, wb[1]);
            pc += pop4(qa2, wa[2]) + pop4(qb2, wb[2]);
            acc[w] += pc;
            qa0 = qa1; qb0 = qb1;
            qa1 = qa2; qb1 = qb2;
        }
    }

    // epilogue: padding corrections + affine
    const int co = co_base + co_sub;
    const float fac = g_factor[co];
    int s[9];
#pragma unroll
    for (int t = 0; t < 9; t++) s[t] = sS[co_sub][t];

    const bool top = (h0 + r) == 0;
    const bool bot = (h0 + r) == H_ - 1;
    int corr_row = 0;
    if (top) corr_row += s[0] + s[1] + s[2];
    if (bot) corr_row += s[6] + s[7] + s[8];

    float* dst = out + ((long)(b * COUT + co)) * HW_ + (h0 + r) * W_ + w0;
#pragma unroll
    for (int w = 0; w < 14; w++) {
        int corr = corr_row;
        int gw = w0 + w;
        if (gw == 0)
            corr += s[3] + (top ? 0 : s[0]) + (bot ? 0 : s[6]);
        if (gw == W_ - 1)
            corr += s[5] + (top ? 0 : s[2]) + (bot ? 0 : s[8]);
        dst[w] = fac * (float)(2304 - 2 * acc[w] - corr);
    }
}

// ---------------------------------------------------------------------------
extern "C" void kernel_launch(void* const* d_in, const int* in_sizes, int n_in,
                              void* d_out, int out_size) {
    const float* x     = (const float*)d_in[0];
    const float* W     = (const float*)d_in[1];
    const float* RV    = (const float*)d_in[2];
    const float* alpha = (const float*)d_in[3];
    float* out = (float*)d_out;

    prep_w_kernel<<<COUT, 256>>>(W, RV, alpha);
    pack_x_kernel<<<dim3(KW, H_, B_), 256>>>(x);
    conv_kernel<<<dim3(4, 4, B_ * 16), 224>>>(out);
}

// round 3
// speedup vs baseline: 1.8882x; 1.1973x over previous
#include <cuda_runtime.h>
#include <cstdint>
#include <cstddef>

// Problem constants
#define B_    32
#define CIN   256
#define COUT  256
#define H_    56
#define W_    56
#define HW_   (H_*W_)          // 3136
#define KS    (COUT*CIN*9)     // stride between weight replicas k

// Padded sign-tensor geometry
#define PADW  58
#define PADN  (PADW*PADW)      // 3364 padded positions per image
#define IMG_N 3712             // rows allocated per image (overhang slack, zeros)
#define GUARD (64*256)         // front guard for negative tap offsets

// Scratch (device globals — zero-initialized, never freed)
__device__ __align__(16) signed char g_sxp[GUARD + (size_t)B_*IMG_N*256];
__device__ __align__(16) signed char g_wi8[COUT*9*CIN];   // [co][tap][ci] = sign(real_w)
__device__ float g_factor[COUT];                          // scale[co]*alpha[co]

// ---------------------------------------------------------------------------
// Kernel A: mix K weight replicas -> int8 signs + per-channel factor
// grid = 256 (co), block = 256 (ci)
// ---------------------------------------------------------------------------
__global__ void prep_w_kernel(const float* __restrict__ W,
                              const float* __restrict__ RV,
                              const float* __restrict__ alpha) {
    const int co = blockIdx.x;
    const int ci = threadIdx.x;
    const float rv0 = RV[0], rv1 = RV[1], rv2 = RV[2], rv3 = RV[3];

    const float* p = W + ((size_t)co * CIN + ci) * 9;
    float asum = 0.f;
#pragma unroll
    for (int t = 0; t < 9; t++) {
        float v = rv0 * p[t] + rv1 * p[t + KS] + rv2 * p[t + 2*KS] + rv3 * p[t + 3*KS];
        asum += fabsf(v);
        g_wi8[(size_t)co*2304 + t*256 + ci] = (v < 0.f) ? (signed char)-1 : (signed char)1;
    }
    __shared__ float red[256];
    red[ci] = asum;
    __syncthreads();
#pragma unroll
    for (int s = 128; s > 0; s >>= 1) {
        if (ci < s) red[ci] += red[ci + s];
        __syncthreads();
    }
    if (ci == 0)
        g_factor[co] = (red[0] * (1.f / 2304.f)) * alpha[co];
}

// ---------------------------------------------------------------------------
// Kernel B: x -> zero-padded int8 sign tensor  sxp[b][h+1][w+1][ci]
// grid = (56 h, 32 b), block = 256. Border rows/cols never written (stay 0).
// ---------------------------------------------------------------------------
__global__ void pack_x_kernel(const float* __restrict__ x) {
    const int h = blockIdx.x;
    const int b = blockIdx.y;
    const int tid = threadIdx.x;

    __shared__ float sx[32][57];
    signed char* dstbase = g_sxp + GUARD + (size_t)b*IMG_N*256
                         + (size_t)(h+1)*PADW*256 + 256;     // (+256): w offset 1

    for (int cb = 0; cb < 8; cb++) {
        for (int i = tid; i < 32*56; i += 256) {
            int cl = i / 56, w = i % 56;
            sx[cl][w] = x[((size_t)(b*CIN + cb*32 + cl))*HW_ + h*W_ + w];
        }
        __syncthreads();
        for (int i = tid; i < 448; i += 256) {
            int w = i >> 3, q = i & 7;       // q = 4-channel group
            unsigned wd = 0;
#pragma unroll
            for (int j = 0; j < 4; j++) {
                unsigned u = __float_as_uint(sx[q*4+j][w]);
                unsigned by = (u >> 31) ? 0xFFu : 0x01u;   // -1 or +1 as s8
                wd |= by << (8*j);
            }
            *(unsigned*)(dstbase + (size_t)w*256 + cb*32 + q*4) = wd;
        }
        __syncthreads();
    }
}

// ---------------------------------------------------------------------------
// Kernel C: int8 implicit-GEMM conv via mma.sync.m16n8k32.s8
// CTA: M=128 (co), N=256 (padded spatial), K=2304 (9 taps x 256 ci)
// 512 threads = 16 warps (4m x 4n), warp tile 32x64.
// 3-stage cp.async pipeline; XOR-swizzled smem for conflict-free ldmatrix.
// grid = (2 co-tiles, 14 n-tiles, 32 b)
// ---------------------------------------------------------------------------
#define STAGES 3
#define KSTEPS 72
#define A_STG  (128*32)
#define B_STG  (256*32)

__device__ __forceinline__ unsigned swz(unsigned row, unsigned c16) {
    return row*32u + 16u*(c16 ^ ((row >> 2) & 1u));
}
__device__ __forceinline__ void cpa16(unsigned dst, const void* src) {
    asm volatile("cp.async.cg.shared.global [%0], [%1], 16;\n" :: "r"(dst), "l"(src));
}

__global__ __launch_bounds__(512, 1)
void gemm_kernel(float* __restrict__ out) {
    const int co0 = blockIdx.x * 128;
    const int n0  = blockIdx.y * 256;
    const int b   = blockIdx.z;
    const int tid = threadIdx.x;
    const int lane = tid & 31;
    const int wid  = tid >> 5;
    const int wm = wid & 3;          // warp row (M)
    const int wn = wid >> 2;         // warp col (N)

    __shared__ signed char As[STAGES][A_STG];
    __shared__ signed char Bs[STAGES][B_STG];

    const signed char* Aglob = g_wi8 + (size_t)co0 * 2304;
    const signed char* Bglob = g_sxp + GUARD + (size_t)b*IMG_N*256 + (size_t)n0*256;

    const unsigned as0 = (unsigned)__cvta_generic_to_shared(&As[0][0]);
    const unsigned bs0 = (unsigned)__cvta_generic_to_shared(&Bs[0][0]);

    // per-thread load coords
    const int lrow = tid >> 1;       // 0..255
    const int lc   = tid & 1;        // 16B chunk

    int acc[2][8][4];
#pragma unroll
    for (int mi = 0; mi < 2; mi++)
#pragma unroll
        for (int ni = 0; ni < 8; ni++)
#pragma unroll
            for (int j = 0; j < 4; j++) acc[mi][ni][j] = 0;

    // ---- async load of one k-step into stage ks%3 ----
    auto issue = [&](int ks) {
        const int stage = ks % STAGES;
        const int tap = ks >> 3, cq = ks & 7;
        const int dy = tap / 3, dx = tap % 3;
        const long bofs = ((long)(dy-1)*PADW + (dx-1))*256 + cq*32;
        // B: 256 rows x 32B
        cpa16(bs0 + stage*B_STG + swz(lrow, lc),
              Bglob + (long)lrow*256 + bofs + lc*16);
        // A: 128 rows x 32B (first 256 threads)
        if (tid < 256)
            cpa16(as0 + stage*A_STG + swz(lrow, lc),
                  Aglob + (long)lrow*2304 + (tap*256 + cq*32) + lc*16);
        asm volatile("cp.async.commit_group;\n");
    };

    issue(0);
    issue(1);

    for (int ks = 0; ks < KSTEPS; ks++) {
        asm volatile("cp.async.wait_group 1;\n");
        __syncthreads();

        const unsigned ab = as0 + (ks % STAGES) * A_STG;
        const unsigned bb = bs0 + (ks % STAGES) * B_STG;

        // A fragments: 2 m16 tiles
        unsigned a[2][4];
#pragma unroll
        for (int mi = 0; mi < 2; mi++) {
            unsigned row = wm*32 + mi*16 + (lane & 15);
            unsigned c16 = (unsigned)lane >> 4;
            unsigned addr = ab + swz(row, c16);
            asm volatile("ldmatrix.sync.aligned.m8n8.x4.shared.b16 {%0,%1,%2,%3}, [%4];\n"
                         : "=r"(a[mi][0]), "=r"(a[mi][1]), "=r"(a[mi][2]), "=r"(a[mi][3])
                         : "r"(addr));
        }
#pragma unroll
        for (int ni = 0; ni < 8; ni++) {
            unsigned row = wn*64 + ni*8 + (lane & 7);
            unsigned c16 = ((unsigned)lane >> 3) & 1;
            unsigned addr = bb + swz(row, c16);
            unsigned bfr0, bfr1;
            asm volatile("ldmatrix.sync.aligned.m8n8.x2.shared.b16 {%0,%1}, [%2];\n"
                         : "=r"(bfr0), "=r"(bfr1) : "r"(addr));
#pragma unroll
            for (int mi = 0; mi < 2; mi++) {
                asm volatile(
                    "mma.sync.aligned.m16n8k32.row.col.s32.s8.s8.s32 "
                    "{%0,%1,%2,%3}, {%4,%5,%6,%7}, {%8,%9}, {%0,%1,%2,%3};\n"
                    : "+r"(acc[mi][ni][0]), "+r"(acc[mi][ni][1]),
                      "+r"(acc[mi][ni][2]), "+r"(acc[mi][ni][3])
                    : "r"(a[mi][0]), "r"(a[mi][1]), "r"(a[mi][2]), "r"(a[mi][3]),
                      "r"(bfr0), "r"(bfr1));
            }
        }

        if (ks + 2 < KSTEPS) issue(ks + 2);
        else asm volatile("cp.async.commit_group;\n");
    }

    // ---- epilogue: scale + scatter to NCHW output, masking padded columns ----
#pragma unroll
    for (int mi = 0; mi < 2; mi++) {
        const int r0 = co0 + wm*32 + mi*16 + (lane >> 2);
        const float f0 = g_factor[r0];
        const float f1 = g_factor[r0 + 8];
        float* o0 = out + ((size_t)(b*COUT + r0))     * HW_;
        float* o1 = out + ((size_t)(b*COUT + r0 + 8)) * HW_;
#pragma unroll
        for (int ni = 0; ni < 8; ni++) {
            const int ncol = n0 + wn*64 + ni*8 + (lane & 3)*2;
#pragma unroll
            for (int j = 0; j < 2; j++) {
                const int n = ncol + j;
                const int h = n / PADW;
                const int w = n - h*PADW;
                if (h >= 1 && h < 57 && w >= 1 && w < 57) {
                    const int oi = (h-1)*W_ + (w-1);
                    o0[oi] = f0 * (float)acc[mi][ni][j];
                    o1[oi] = f1 * (float)acc[mi][ni][2+j];
                }
            }
        }
    }
}

// ---------------------------------------------------------------------------
extern "C" void kernel_launch(void* const* d_in, const int* in_sizes, int n_in,
                              void* d_out, int out_size) {
    const float* x     = (const float*)d_in[0];
    const float* W     = (const float*)d_in[1];
    const float* RV    = (const float*)d_in[2];
    const float* alpha = (const float*)d_in[3];
    float* out = (float*)d_out;

    prep_w_kernel<<<COUT, 256>>>(W, RV, alpha);
    pack_x_kernel<<<dim3(H_, B_), 256>>>(x);
    gemm_kernel<<<dim3(2, 14, B_), 512>>>(out);
}